// round 1
// baseline (speedup 1.0000x reference)
#include <cuda_runtime.h>
#include <cstdint>

// Problem constants
#define NROWS  16384   // B*H*W = 16*32*32
#define NCODES 8192
#define DIMD   256
#define HWQ    1024    // H*W
#define ZQ_ELEMS 4194304  // 16*256*32*32

// Scratch (no allocations allowed -> device globals)
__device__ unsigned long long g_best[NROWS];
__device__ float g_a[NROWS];
__device__ float g_bsq[NCODES];
__device__ int   g_idx[NROWS];
__device__ float g_loss;

__device__ __forceinline__ unsigned long long pack2f(float lo, float hi) {
    unsigned long long r;
    asm("mov.b64 %0, {%1, %2};" : "=l"(r) : "f"(lo), "f"(hi));
    return r;
}
__device__ __forceinline__ void unpack2f(unsigned long long v, float &lo, float &hi) {
    asm("mov.b64 {%0, %1}, %2;" : "=f"(lo), "=f"(hi) : "l"(v));
}
__device__ __forceinline__ void fma_x2(unsigned long long &acc, unsigned long long a, unsigned long long b) {
    asm("fma.rn.f32x2 %0, %1, %2, %0;" : "+l"(acc) : "l"(a), "l"(b));
}

__global__ void k_init() {
    int i = blockIdx.x * blockDim.x + threadIdx.x;
    if (i < NROWS) g_best[i] = 0xFFFFFFFFFFFFFFFFULL;
    if (i == 0) g_loss = 0.0f;
}

// a[n] = sum_d z[n,d]^2  ; z layout (B, D, H, W): z_flat[n,d] = z[b, d, p], n = b*1024 + p
__global__ void k_rownorm_z(const float* __restrict__ z) {
    int n = blockIdx.x * blockDim.x + threadIdx.x;
    if (n >= NROWS) return;
    int b = n >> 10, p = n & 1023;
    const float* zp = z + (size_t)b * DIMD * HWQ + p;
    float s = 0.0f;
#pragma unroll 8
    for (int d = 0; d < DIMD; d++) {
        float v = zp[(size_t)d * HWQ];
        s = fmaf(v, v, s);
    }
    g_a[n] = s;
}

__global__ void k_rownorm_cb(const float* __restrict__ cb) {
    int k = blockIdx.x * blockDim.x + threadIdx.x;
    if (k >= NCODES) return;
    const float4* row = reinterpret_cast<const float4*>(cb + (size_t)k * DIMD);
    float s = 0.0f;
#pragma unroll
    for (int q = 0; q < DIMD / 4; q++) {
        float4 v = row[q];
        s = fmaf(v.x, v.x, s); s = fmaf(v.y, v.y, s);
        s = fmaf(v.z, v.z, s); s = fmaf(v.w, v.w, s);
    }
    g_bsq[k] = s;
}

// Fused fp32 GEMM (dot products) + distance + argmin.
// CTA tile: 128 rows x 128 codes, 256 threads, 8x8 micro-tile,
// f32x2 packed FMA pairing adjacent codes. Double-buffered smem, D-chunks of 16.
__global__ void __launch_bounds__(256, 2) k_gemm_argmin(
    const float* __restrict__ z, const float* __restrict__ cb)
{
    __shared__ float As[2][16][128];
    __shared__ float Bs[2][16][128];

    const int t  = threadIdx.x;
    const int m0 = blockIdx.y * 128;    // row tile
    const int k0 = blockIdx.x * 128;    // code tile
    const int b  = m0 >> 10;
    const int p0 = m0 & 1023;
    const float* zb = z + (size_t)b * DIMD * HWQ + p0;

    const int tx = t & 15;   // code group (8 codes each)
    const int ty = t >> 4;   // row group (8 rows each)

    // global-load assignments
    const int la_d = t >> 5;          // 0..7
    const int la_r = (t & 31) * 4;    // 0..124
    const int lb_c = t >> 1;          // 0..127
    const int lb_d = (t & 1) * 8;     // 0 or 8

    unsigned long long acc[8][4];
#pragma unroll
    for (int i = 0; i < 8; i++)
#pragma unroll
        for (int j = 0; j < 4; j++) acc[i][j] = 0ULL;

    float4 ra[2], rb[2];
    // prologue: load chunk 0
    {
#pragma unroll
        for (int h = 0; h < 2; h++) {
            int d = la_d + h * 8;
            ra[h] = *reinterpret_cast<const float4*>(zb + (size_t)d * HWQ + la_r);
        }
        const float* base = cb + (size_t)(k0 + lb_c) * DIMD + lb_d;
        rb[0] = *reinterpret_cast<const float4*>(base);
        rb[1] = *reinterpret_cast<const float4*>(base + 4);
        // store to buffer 0
#pragma unroll
        for (int h = 0; h < 2; h++)
            *reinterpret_cast<float4*>(&As[0][la_d + h * 8][la_r]) = ra[h];
#pragma unroll
        for (int h = 0; h < 2; h++) {
            float4 v = rb[h];
            int d = lb_d + h * 4;
            Bs[0][d + 0][lb_c] = v.x;
            Bs[0][d + 1][lb_c] = v.y;
            Bs[0][d + 2][lb_c] = v.z;
            Bs[0][d + 3][lb_c] = v.w;
        }
    }
    __syncthreads();

#pragma unroll 1
    for (int c = 0; c < 16; c++) {
        // prefetch next chunk into registers
        if (c < 15) {
            int dc = (c + 1) * 16;
#pragma unroll
            for (int h = 0; h < 2; h++) {
                int d = dc + la_d + h * 8;
                ra[h] = *reinterpret_cast<const float4*>(zb + (size_t)d * HWQ + la_r);
            }
            const float* base = cb + (size_t)(k0 + lb_c) * DIMD + dc + lb_d;
            rb[0] = *reinterpret_cast<const float4*>(base);
            rb[1] = *reinterpret_cast<const float4*>(base + 4);
        }
        // compute on buffer c&1
        const int buf = c & 1;
#pragma unroll
        for (int s = 0; s < 16; s++) {
            float4 a0 = *reinterpret_cast<const float4*>(&As[buf][s][ty * 8]);
            float4 a1 = *reinterpret_cast<const float4*>(&As[buf][s][ty * 8 + 4]);
            float4 b0 = *reinterpret_cast<const float4*>(&Bs[buf][s][tx * 8]);
            float4 b1 = *reinterpret_cast<const float4*>(&Bs[buf][s][tx * 8 + 4]);
            unsigned long long bp[4];
            bp[0] = pack2f(b0.x, b0.y);
            bp[1] = pack2f(b0.z, b0.w);
            bp[2] = pack2f(b1.x, b1.y);
            bp[3] = pack2f(b1.z, b1.w);
            float av[8] = {a0.x, a0.y, a0.z, a0.w, a1.x, a1.y, a1.z, a1.w};
#pragma unroll
            for (int i = 0; i < 8; i++) {
                unsigned long long ap = pack2f(av[i], av[i]);
#pragma unroll
                for (int j = 0; j < 4; j++) fma_x2(acc[i][j], ap, bp[j]);
            }
        }
        if (c < 15) {
            const int nb = (c + 1) & 1;
#pragma unroll
            for (int h = 0; h < 2; h++)
                *reinterpret_cast<float4*>(&As[nb][la_d + h * 8][la_r]) = ra[h];
#pragma unroll
            for (int h = 0; h < 2; h++) {
                float4 v = rb[h];
                int d = lb_d + h * 4;
                Bs[nb][d + 0][lb_c] = v.x;
                Bs[nb][d + 1][lb_c] = v.y;
                Bs[nb][d + 2][lb_c] = v.z;
                Bs[nb][d + 3][lb_c] = v.w;
            }
            __syncthreads();
        }
    }

    // Epilogue: dist = fl(fl(a + b) - 2*dot), argmin with first-wins ties.
    float arow[8], bcol[8];
#pragma unroll
    for (int i = 0; i < 8; i++) arow[i] = g_a[m0 + ty * 8 + i];
#pragma unroll
    for (int j = 0; j < 8; j++) bcol[j] = g_bsq[k0 + tx * 8 + j];

#pragma unroll
    for (int i = 0; i < 8; i++) {
        unsigned long long best = 0xFFFFFFFFFFFFFFFFULL;
#pragma unroll
        for (int jp = 0; jp < 4; jp++) {
            float lo, hi;
            unpack2f(acc[i][jp], lo, hi);
            int j0 = jp * 2;
            float t0 = __fadd_rn(arow[i], bcol[j0]);
            float t1 = __fadd_rn(arow[i], bcol[j0 + 1]);
            float d0 = __fadd_rn(t0, -2.0f * lo);
            float d1 = __fadd_rn(t1, -2.0f * hi);
            unsigned kk0 = (unsigned)(k0 + tx * 8 + j0);
            unsigned long long key0 = ((unsigned long long)__float_as_uint(d0) << 32) | kk0;
            unsigned long long key1 = ((unsigned long long)__float_as_uint(d1) << 32) | (kk0 + 1);
            if (key0 < best) best = key0;
            if (key1 < best) best = key1;
        }
#pragma unroll
        for (int off = 8; off; off >>= 1) {
            unsigned long long o = __shfl_xor_sync(0xFFFFFFFFu, best, off);
            if (o < best) best = o;
        }
        if (tx == 0) atomicMin(&g_best[m0 + ty * 8 + i], best);
    }
}

__global__ void k_indices(float* __restrict__ out, int out_size) {
    int n = blockIdx.x * blockDim.x + threadIdx.x;
    if (n >= NROWS) return;
    int idx = (int)(g_best[n] & 0xFFFFFFFFULL);
    g_idx[n] = idx;
    if (out_size >= ZQ_ELEMS + NROWS) out[ZQ_ELEMS + n] = (float)idx;
}

// z_q_st = fl(z + fl(z_q - z)); also accumulate sum((z_q - z)^2)
__global__ void k_output(const float* __restrict__ z, const float* __restrict__ cb,
                         float* __restrict__ out, int out_size) {
    int i = blockIdx.x * blockDim.x + threadIdx.x;
    float dsq = 0.0f;
    if (i < ZQ_ELEMS) {
        int p = i & 1023;
        int d = (i >> 10) & 255;
        int b = i >> 18;
        int n = (b << 10) | p;
        int idx = g_idx[n];
        float zv = z[i];
        float e  = cb[(size_t)idx * DIMD + d];
        float diff = __fadd_rn(e, -zv);
        if (i < out_size) out[i] = __fadd_rn(zv, diff);
        dsq = diff * diff;
    }
#pragma unroll
    for (int off = 16; off; off >>= 1)
        dsq += __shfl_xor_sync(0xFFFFFFFFu, dsq, off);
    __shared__ float warpsum[8];
    int lane = threadIdx.x & 31, w = threadIdx.x >> 5;
    if (lane == 0) warpsum[w] = dsq;
    __syncthreads();
    if (threadIdx.x == 0) {
        float s = 0.0f;
#pragma unroll
        for (int q = 0; q < 8; q++) s += warpsum[q];
        atomicAdd(&g_loss, s);
    }
}

__global__ void k_loss(float* __restrict__ out, int out_size) {
    if (out_size >= ZQ_ELEMS + NROWS + 1) {
        float mean = g_loss / (float)ZQ_ELEMS;
        out[ZQ_ELEMS + NROWS] = 0.25f * mean;
    }
}

extern "C" void kernel_launch(void* const* d_in, const int* in_sizes, int n_in,
                              void* d_out, int out_size) {
    const float* z;
    const float* cb;
    if (n_in >= 2 && in_sizes[0] == ZQ_ELEMS) {
        z = (const float*)d_in[0]; cb = (const float*)d_in[1];
    } else {
        z = (const float*)d_in[1]; cb = (const float*)d_in[0];
    }
    float* out = (float*)d_out;

    k_init<<<(NROWS + 255) / 256, 256>>>();
    k_rownorm_z<<<(NROWS + 255) / 256, 256>>>(z);
    k_rownorm_cb<<<(NCODES + 255) / 256, 256>>>(cb);

    dim3 grid(NCODES / 128, NROWS / 128);  // (64, 128)
    k_gemm_argmin<<<grid, 256>>>(z, cb);

    k_indices<<<(NROWS + 255) / 256, 256>>>(out, out_size);
    k_output<<<(ZQ_ELEMS + 255) / 256, 256>>>(z, cb, out, out_size);
    k_loss<<<1, 1>>>(out, out_size);
}

// round 2
// speedup vs baseline: 1.6380x; 1.6380x over previous
#include <cuda_runtime.h>
#include <cstdint>

// Problem constants
#define NROWS  16384   // B*H*W = 16*32*32
#define NCODES 8192
#define DIMD   256
#define HWQ    1024    // H*W
#define ZQ_ELEMS 4194304  // 16*256*32*32

// Scratch (no allocations allowed -> device globals)
__device__ unsigned long long g_best[NROWS];
__device__ float g_a[NROWS];
__device__ float g_bsq[NCODES];
__device__ int   g_idx[NROWS];
__device__ float g_loss;

__device__ __forceinline__ unsigned long long pack2f(float lo, float hi) {
    unsigned long long r;
    asm("mov.b64 %0, {%1, %2};" : "=l"(r) : "f"(lo), "f"(hi));
    return r;
}
__device__ __forceinline__ void unpack2f(unsigned long long v, float &lo, float &hi) {
    asm("mov.b64 {%0, %1}, %2;" : "=f"(lo), "=f"(hi) : "l"(v));
}
__device__ __forceinline__ void fma_x2(unsigned long long &acc, unsigned long long a, unsigned long long b) {
    asm("fma.rn.f32x2 %0, %1, %2, %0;" : "+l"(acc) : "l"(a), "l"(b));
}

__global__ void k_init() {
    int i = blockIdx.x * blockDim.x + threadIdx.x;
    if (i < NROWS) g_best[i] = 0xFFFFFFFFFFFFFFFFULL;
    if (i == 0) g_loss = 0.0f;
}

// a[n] = sum_d z[n,d]^2  ; z layout (B, D, H, W): z_flat[n,d] = z[b, d, p], n = b*1024 + p
__global__ void k_rownorm_z(const float* __restrict__ z) {
    int n = blockIdx.x * blockDim.x + threadIdx.x;
    if (n >= NROWS) return;
    int b = n >> 10, p = n & 1023;
    const float* zp = z + (size_t)b * DIMD * HWQ + p;
    float s = 0.0f;
#pragma unroll 8
    for (int d = 0; d < DIMD; d++) {
        float v = zp[(size_t)d * HWQ];
        s = fmaf(v, v, s);
    }
    g_a[n] = s;
}

__global__ void k_rownorm_cb(const float* __restrict__ cb) {
    int k = blockIdx.x * blockDim.x + threadIdx.x;
    if (k >= NCODES) return;
    const float4* row = reinterpret_cast<const float4*>(cb + (size_t)k * DIMD);
    float s = 0.0f;
#pragma unroll
    for (int q = 0; q < DIMD / 4; q++) {
        float4 v = row[q];
        s = fmaf(v.x, v.x, s); s = fmaf(v.y, v.y, s);
        s = fmaf(v.z, v.z, s); s = fmaf(v.w, v.w, s);
    }
    g_bsq[k] = s;
}

// Fused fp32 GEMM (dot products) + distance + argmin.
// CTA tile: 128 rows x 128 codes, 256 threads, 8x8 micro-tile,
// f32x2 packed FMA pairing adjacent codes. Double-buffered smem, D-chunks of 16.
__global__ void __launch_bounds__(256, 2) k_gemm_argmin(
    const float* __restrict__ z, const float* __restrict__ cb)
{
    __shared__ float As[2][16][128];
    __shared__ float Bs[2][16][128];

    const int t  = threadIdx.x;
    const int m0 = blockIdx.y * 128;    // row tile
    const int k0 = blockIdx.x * 128;    // code tile
    const int b  = m0 >> 10;
    const int p0 = m0 & 1023;
    const float* zb = z + (size_t)b * DIMD * HWQ + p0;

    const int tx = t & 15;   // code group (8 codes each)
    const int ty = t >> 4;   // row group (8 rows each)

    // global-load assignments
    const int la_d = t >> 5;          // 0..7
    const int la_r = (t & 31) * 4;    // 0..124
    const int lb_c = t >> 1;          // 0..127
    const int lb_d = (t & 1) * 8;     // 0 or 8

    unsigned long long acc[8][4];
#pragma unroll
    for (int i = 0; i < 8; i++)
#pragma unroll
        for (int j = 0; j < 4; j++) acc[i][j] = 0ULL;

    float4 ra[2], rb[2];
    // prologue: load chunk 0
    {
#pragma unroll
        for (int h = 0; h < 2; h++) {
            int d = la_d + h * 8;
            ra[h] = *reinterpret_cast<const float4*>(zb + (size_t)d * HWQ + la_r);
        }
        const float* base = cb + (size_t)(k0 + lb_c) * DIMD + lb_d;
        rb[0] = *reinterpret_cast<const float4*>(base);
        rb[1] = *reinterpret_cast<const float4*>(base + 4);
        // store to buffer 0
#pragma unroll
        for (int h = 0; h < 2; h++)
            *reinterpret_cast<float4*>(&As[0][la_d + h * 8][la_r]) = ra[h];
#pragma unroll
        for (int h = 0; h < 2; h++) {
            float4 v = rb[h];
            int d = lb_d + h * 4;
            Bs[0][d + 0][lb_c] = v.x;
            Bs[0][d + 1][lb_c] = v.y;
            Bs[0][d + 2][lb_c] = v.z;
            Bs[0][d + 3][lb_c] = v.w;
        }
    }
    __syncthreads();

#pragma unroll 1
    for (int c = 0; c < 16; c++) {
        // prefetch next chunk into registers
        if (c < 15) {
            int dc = (c + 1) * 16;
#pragma unroll
            for (int h = 0; h < 2; h++) {
                int d = dc + la_d + h * 8;
                ra[h] = *reinterpret_cast<const float4*>(zb + (size_t)d * HWQ + la_r);
            }
            const float* base = cb + (size_t)(k0 + lb_c) * DIMD + dc + lb_d;
            rb[0] = *reinterpret_cast<const float4*>(base);
            rb[1] = *reinterpret_cast<const float4*>(base + 4);
        }
        // compute on buffer c&1
        const int buf = c & 1;
#pragma unroll
        for (int s = 0; s < 16; s++) {
            float4 a0 = *reinterpret_cast<const float4*>(&As[buf][s][ty * 8]);
            float4 a1 = *reinterpret_cast<const float4*>(&As[buf][s][ty * 8 + 4]);
            float4 b0 = *reinterpret_cast<const float4*>(&Bs[buf][s][tx * 8]);
            float4 b1 = *reinterpret_cast<const float4*>(&Bs[buf][s][tx * 8 + 4]);
            unsigned long long bp[4];
            bp[0] = pack2f(b0.x, b0.y);
            bp[1] = pack2f(b0.z, b0.w);
            bp[2] = pack2f(b1.x, b1.y);
            bp[3] = pack2f(b1.z, b1.w);
            float av[8] = {a0.x, a0.y, a0.z, a0.w, a1.x, a1.y, a1.z, a1.w};
#pragma unroll
            for (int i = 0; i < 8; i++) {
                unsigned long long ap = pack2f(av[i], av[i]);
#pragma unroll
                for (int j = 0; j < 4; j++) fma_x2(acc[i][j], ap, bp[j]);
            }
        }
        if (c < 15) {
            const int nb = (c + 1) & 1;
#pragma unroll
            for (int h = 0; h < 2; h++)
                *reinterpret_cast<float4*>(&As[nb][la_d + h * 8][la_r]) = ra[h];
#pragma unroll
            for (int h = 0; h < 2; h++) {
                float4 v = rb[h];
                int d = lb_d + h * 4;
                Bs[nb][d + 0][lb_c] = v.x;
                Bs[nb][d + 1][lb_c] = v.y;
                Bs[nb][d + 2][lb_c] = v.z;
                Bs[nb][d + 3][lb_c] = v.w;
            }
            __syncthreads();
        }
    }

    // Epilogue: dist = fl(fl(a + b) - 2*dot), argmin with first-wins ties.
    float arow[8], bcol[8];
#pragma unroll
    for (int i = 0; i < 8; i++) arow[i] = g_a[m0 + ty * 8 + i];
#pragma unroll
    for (int j = 0; j < 8; j++) bcol[j] = g_bsq[k0 + tx * 8 + j];

#pragma unroll
    for (int i = 0; i < 8; i++) {
        unsigned long long best = 0xFFFFFFFFFFFFFFFFULL;
#pragma unroll
        for (int jp = 0; jp < 4; jp++) {
            float lo, hi;
            unpack2f(acc[i][jp], lo, hi);
            int j0 = jp * 2;
            float t0 = __fadd_rn(arow[i], bcol[j0]);
            float t1 = __fadd_rn(arow[i], bcol[j0 + 1]);
            float d0 = __fadd_rn(t0, -2.0f * lo);
            float d1 = __fadd_rn(t1, -2.0f * hi);
            unsigned kk0 = (unsigned)(k0 + tx * 8 + j0);
            unsigned long long key0 = ((unsigned long long)__float_as_uint(d0) << 32) | kk0;
            unsigned long long key1 = ((unsigned long long)__float_as_uint(d1) << 32) | (kk0 + 1);
            if (key0 < best) best = key0;
            if (key1 < best) best = key1;
        }
#pragma unroll
        for (int off = 8; off; off >>= 1) {
            unsigned long long o = __shfl_xor_sync(0xFFFFFFFFu, best, off);
            if (o < best) best = o;
        }
        if (tx == 0) atomicMin(&g_best[m0 + ty * 8 + i], best);
    }
}

__global__ void k_indices(float* __restrict__ out, int out_size) {
    int n = blockIdx.x * blockDim.x + threadIdx.x;
    if (n >= NROWS) return;
    int idx = (int)(g_best[n] & 0xFFFFFFFFULL);
    g_idx[n] = idx;
    if (out_size >= ZQ_ELEMS + NROWS) out[ZQ_ELEMS + n] = (float)idx;
}

// z_q_st = fl(z + fl(z_q - z)); also accumulate sum((z_q - z)^2)
__global__ void k_output(const float* __restrict__ z, const float* __restrict__ cb,
                         float* __restrict__ out, int out_size) {
    int i = blockIdx.x * blockDim.x + threadIdx.x;
    float dsq = 0.0f;
    if (i < ZQ_ELEMS) {
        int p = i & 1023;
        int d = (i >> 10) & 255;
        int b = i >> 18;
        int n = (b << 10) | p;
        int idx = g_idx[n];
        float zv = z[i];
        float e  = cb[(size_t)idx * DIMD + d];
        float diff = __fadd_rn(e, -zv);
        if (i < out_size) out[i] = __fadd_rn(zv, diff);
        dsq = diff * diff;
    }
#pragma unroll
    for (int off = 16; off; off >>= 1)
        dsq += __shfl_xor_sync(0xFFFFFFFFu, dsq, off);
    __shared__ float warpsum[8];
    int lane = threadIdx.x & 31, w = threadIdx.x >> 5;
    if (lane == 0) warpsum[w] = dsq;
    __syncthreads();
    if (threadIdx.x == 0) {
        float s = 0.0f;
#pragma unroll
        for (int q = 0; q < 8; q++) s += warpsum[q];
        atomicAdd(&g_loss, s);
    }
}

__global__ void k_loss(float* __restrict__ out, int out_size) {
    if (out_size >= ZQ_ELEMS + NROWS + 1) {
        float mean = g_loss / (float)ZQ_ELEMS;
        out[ZQ_ELEMS + NROWS] = 0.25f * mean;
    }
}

extern "C" void kernel_launch(void* const* d_in, const int* in_sizes, int n_in,
                              void* d_out, int out_size) {
    const float* z;
    const float* cb;
    if (n_in >= 2 && in_sizes[0] == ZQ_ELEMS) {
        z = (const float*)d_in[0]; cb = (const float*)d_in[1];
    } else {
        z = (const float*)d_in[1]; cb = (const float*)d_in[0];
    }
    float* out = (float*)d_out;

    k_init<<<(NROWS + 255) / 256, 256>>>();
    k_rownorm_z<<<(NROWS + 255) / 256, 256>>>(z);
    k_rownorm_cb<<<(NCODES + 255) / 256, 256>>>(cb);

    dim3 grid(NCODES / 128, NROWS / 128);  // (64, 128)
    k_gemm_argmin<<<grid, 256>>>(z, cb);

    k_indices<<<(NROWS + 255) / 256, 256>>>(out, out_size);
    k_output<<<(ZQ_ELEMS + 255) / 256, 256>>>(z, cb, out, out_size);
    k_loss<<<1, 1>>>(out, out_size);
}

// round 4
// speedup vs baseline: 4.3625x; 2.6632x over previous
#include <cuda_runtime.h>
#include <cuda_bf16.h>
#include <cstdint>

#define NROWS    16384
#define NCODES   8192
#define DIMD     256
#define HWQ      1024
#define ZQ_ELEMS 4194304
#define MARGIN   2e-4f

// Scratch (device globals; no allocations allowed)
__device__ __align__(16) __nv_bfloat16 g_zbf[NROWS * DIMD];    // 8 MB
__device__ __align__(16) __nv_bfloat16 g_cbbf[NCODES * DIMD];  // 4 MB
__device__ __align__(16) float         g_zt[NROWS * DIMD];     // 16 MB (exact fp32, row-major)
__device__ float g_bsq[NCODES];
__device__ __align__(16) __nv_bfloat16 g_scores[(size_t)NROWS * NCODES]; // 256 MB bf16 spill
__device__ int   g_idx[NROWS];
__device__ float g_loss;

// ---------------- helpers ----------------
__device__ __forceinline__ uint32_t smem_u32(const void* p) {
    uint32_t a;
    asm("{ .reg .u64 t; cvta.to.shared.u64 t, %1; cvt.u32.u64 %0, t; }" : "=r"(a) : "l"(p));
    return a;
}
__device__ __forceinline__ uint32_t swz(uint32_t off) { return off ^ ((off >> 3) & 0x70); }

#define CP_ASYNC16(dst, src) \
    asm volatile("cp.async.cg.shared.global [%0], [%1], 16;" :: "r"(dst), "l"(src) : "memory")
#define CP_COMMIT() asm volatile("cp.async.commit_group;" ::: "memory")

#define LDSM_X4(r0, r1, r2, r3, addr) \
    asm volatile("ldmatrix.sync.aligned.m8n8.x4.shared.b16 {%0,%1,%2,%3}, [%4];" \
        : "=r"(r0), "=r"(r1), "=r"(r2), "=r"(r3) : "r"(addr))

#define MMA16816(d, a, b0, b1) \
    asm volatile("mma.sync.aligned.m16n8k16.row.col.f32.bf16.bf16.f32 " \
        "{%0,%1,%2,%3}, {%4,%5,%6,%7}, {%8,%9}, {%0,%1,%2,%3};" \
        : "+f"((d)[0]), "+f"((d)[1]), "+f"((d)[2]), "+f"((d)[3]) \
        : "r"((a)[0]), "r"((a)[1]), "r"((a)[2]), "r"((a)[3]), "r"(b0), "r"(b1))

__device__ __forceinline__ float bf_lo(uint32_t u) { return __uint_as_float(u << 16); }
__device__ __forceinline__ float bf_hi(uint32_t u) { return __uint_as_float(u & 0xFFFF0000u); }

// ---------------- prep kernels ----------------
// z (B,D,H,W) -> z_t [n][d] fp32 (exact transpose)
__global__ void k_prep_zt(const float* __restrict__ z) {
    int i = blockIdx.x * blockDim.x + threadIdx.x;
    if (i == 0) g_loss = 0.0f;
    if (i >= ZQ_ELEMS) return;
    int b = i >> 18, d = (i >> 10) & 255, p = i & 1023;
    g_zt[(size_t)((b << 10) | p) * DIMD + d] = z[i];
}
// z_t -> zbf (bf16)
__global__ void k_prep_zbf() {
    int u = blockIdx.x * blockDim.x + threadIdx.x;
    if (u >= NROWS * 32) return;
    int n = u >> 5, d8 = (u & 31) * 8;
    const float4* src = reinterpret_cast<const float4*>(g_zt + (size_t)n * DIMD + d8);
    float4 f0 = src[0], f1 = src[1];
    __nv_bfloat162 h0 = __floats2bfloat162_rn(f0.x, f0.y);
    __nv_bfloat162 h1 = __floats2bfloat162_rn(f0.z, f0.w);
    __nv_bfloat162 h2 = __floats2bfloat162_rn(f1.x, f1.y);
    __nv_bfloat162 h3 = __floats2bfloat162_rn(f1.z, f1.w);
    uint4 q;
    q.x = *reinterpret_cast<uint32_t*>(&h0);
    q.y = *reinterpret_cast<uint32_t*>(&h1);
    q.z = *reinterpret_cast<uint32_t*>(&h2);
    q.w = *reinterpret_cast<uint32_t*>(&h3);
    *reinterpret_cast<uint4*>(g_zbf + (size_t)n * DIMD + d8) = q;
}
// cb -> cbbf (bf16)
__global__ void k_prep_cb(const float* __restrict__ cb) {
    int u = blockIdx.x * blockDim.x + threadIdx.x;
    if (u >= NCODES * 32) return;
    int k = u >> 5, d8 = (u & 31) * 8;
    const float4* src = reinterpret_cast<const float4*>(cb + (size_t)k * DIMD + d8);
    float4 f0 = src[0], f1 = src[1];
    __nv_bfloat162 h0 = __floats2bfloat162_rn(f0.x, f0.y);
    __nv_bfloat162 h1 = __floats2bfloat162_rn(f0.z, f0.w);
    __nv_bfloat162 h2 = __floats2bfloat162_rn(f1.x, f1.y);
    __nv_bfloat162 h3 = __floats2bfloat162_rn(f1.z, f1.w);
    uint4 q;
    q.x = *reinterpret_cast<uint32_t*>(&h0);
    q.y = *reinterpret_cast<uint32_t*>(&h1);
    q.z = *reinterpret_cast<uint32_t*>(&h2);
    q.w = *reinterpret_cast<uint32_t*>(&h3);
    *reinterpret_cast<uint4*>(g_cbbf + (size_t)k * DIMD + d8) = q;
}
__global__ void k_bsq(const float* __restrict__ cb) {
    int k = blockIdx.x * blockDim.x + threadIdx.x;
    if (k >= NCODES) return;
    const float4* row = reinterpret_cast<const float4*>(cb + (size_t)k * DIMD);
    float s = 0.0f;
#pragma unroll
    for (int q = 0; q < DIMD / 4; q++) {
        float4 v = row[q];
        s = fmaf(v.x, v.x, s); s = fmaf(v.y, v.y, s);
        s = fmaf(v.z, v.z, s); s = fmaf(v.w, v.w, s);
    }
    g_bsq[k] = s;
}

// ---------------- bf16 HMMA screening GEMM ----------------
// S[m][n] = 2 * zbf[m,:].cbbf[n,:] - bsq[n], stored bf16.
// CTA 128x128, 8 warps (2x4) of 64x32, K-chunks of 64, double-buffered cp.async.
__global__ void __launch_bounds__(256, 2) k_gemm() {
    extern __shared__ __align__(1024) unsigned char smem[];
    const uint32_t sA = smem_u32(smem);        // 2 x 16KB
    const uint32_t sB = sA + 32768;            // 2 x 16KB

    const int t = threadIdx.x;
    const int lane = t & 31, wid = t >> 5;
    const int wy = wid >> 2, wx = wid & 3;
    const int m0 = blockIdx.y * 128, n0 = blockIdx.x * 128;

    const char* gA = (const char*)(g_zbf  + (size_t)m0 * DIMD);
    const char* gB = (const char*)(g_cbbf + (size_t)n0 * DIMD);

    // per-thread cp.async slots: 4 x 16B per tile
    const int ld_row[4] = { (t + 0) >> 3, (t + 256) >> 3, (t + 512) >> 3, (t + 768) >> 3 };
    const int ld_seg = t & 7;

    float acc[4][4][4];
#pragma unroll
    for (int a = 0; a < 4; a++)
#pragma unroll
        for (int b = 0; b < 4; b++)
#pragma unroll
            for (int c = 0; c < 4; c++) acc[a][b][c] = 0.0f;

#define ISSUE(c) do {                                                           \
    uint32_t dA = sA + ((c) & 1) * 16384;                                       \
    uint32_t dB = sB + ((c) & 1) * 16384;                                       \
    _Pragma("unroll")                                                           \
    for (int i = 0; i < 4; i++) {                                               \
        uint32_t off = swz((uint32_t)(ld_row[i] * 128 + ld_seg * 16));          \
        size_t go = (size_t)ld_row[i] * 512 + (c) * 128 + ld_seg * 16;          \
        CP_ASYNC16(dA + off, gA + go);                                          \
        CP_ASYNC16(dB + off, gB + go);                                          \
    }                                                                           \
    CP_COMMIT();                                                                \
} while (0)

    ISSUE(0);
    ISSUE(1);

    const int g = lane >> 3, r = lane & 7;
    const int aRow = wy * 64 + (g & 1) * 8 + r;
    const int bRow = wx * 32 + (g & 1) * 8 + r;
    const int kCol = (g >> 1) * 8;

#pragma unroll 1
    for (int c = 0; c < 4; c++) {
        if (c < 3) asm volatile("cp.async.wait_group 1;" ::: "memory");
        else       asm volatile("cp.async.wait_group 0;" ::: "memory");
        __syncthreads();

        const uint32_t bA = sA + (c & 1) * 16384;
        const uint32_t bB = sB + (c & 1) * 16384;
#pragma unroll
        for (int ks = 0; ks < 4; ks++) {
            uint32_t af[4][4], bf[2][4];
#pragma unroll
            for (int mt = 0; mt < 4; mt++) {
                uint32_t off = (uint32_t)((aRow + mt * 16) * 128 + (kCol + ks * 16) * 2);
                LDSM_X4(af[mt][0], af[mt][1], af[mt][2], af[mt][3], bA + swz(off));
            }
#pragma unroll
            for (int bt = 0; bt < 2; bt++) {
                uint32_t off = (uint32_t)((bRow + bt * 16) * 128 + (kCol + ks * 16) * 2);
                LDSM_X4(bf[bt][0], bf[bt][1], bf[bt][2], bf[bt][3], bB + swz(off));
            }
#pragma unroll
            for (int mt = 0; mt < 4; mt++)
#pragma unroll
                for (int bt = 0; bt < 2; bt++) {
                    MMA16816(acc[mt][bt * 2 + 0], af[mt], bf[bt][0], bf[bt][2]);
                    MMA16816(acc[mt][bt * 2 + 1], af[mt], bf[bt][1], bf[bt][3]);
                }
        }
        __syncthreads();
        if (c < 2) ISSUE(c + 2);
    }

    // epilogue: s = 2*dot - bsq -> bf16 spill
    const int cRow = lane >> 2, cCol = (lane & 3) * 2;
#pragma unroll
    for (int mt = 0; mt < 4; mt++) {
        int r0 = m0 + wy * 64 + mt * 16 + cRow;
#pragma unroll
        for (int nn = 0; nn < 4; nn++) {
            int col = n0 + wx * 32 + nn * 8 + cCol;
            float b0 = g_bsq[col], b1 = g_bsq[col + 1];
            float s00 = fmaf(2.0f, acc[mt][nn][0], -b0);
            float s01 = fmaf(2.0f, acc[mt][nn][1], -b1);
            float s10 = fmaf(2.0f, acc[mt][nn][2], -b0);
            float s11 = fmaf(2.0f, acc[mt][nn][3], -b1);
            __nv_bfloat162 p0 = __floats2bfloat162_rn(s00, s01);
            __nv_bfloat162 p1 = __floats2bfloat162_rn(s10, s11);
            *reinterpret_cast<uint32_t*>((char*)g_scores + ((size_t)r0 * NCODES + col) * 2) =
                *reinterpret_cast<uint32_t*>(&p0);
            *reinterpret_cast<uint32_t*>((char*)g_scores + ((size_t)(r0 + 8) * NCODES + col) * 2) =
                *reinterpret_cast<uint32_t*>(&p1);
        }
    }
#undef ISSUE
}

// ---------------- scan + exact fp32 rescue ----------------
// one warp per row: max over 8192 bf16 scores, candidates >= max - MARGIN,
// exact fp32 rescore, first-wins argmin.
__global__ void __launch_bounds__(256) void_guard();
__global__ void __launch_bounds__(256) k_scan(const float* __restrict__ cb,
                                              float* __restrict__ out, int out_size) {
    extern __shared__ __align__(16) unsigned char ssc[];   // 8 x 16KB score rows
    __shared__ int            s_cnt[8];
    __shared__ unsigned short s_cand[8][32];

    const int w = threadIdx.x >> 5, lane = threadIdx.x & 31;
    const int row = blockIdx.x * 8 + w;
    if (lane == 0) s_cnt[w] = 0;
    __syncwarp();

    uint4* srow = reinterpret_cast<uint4*>(ssc + (size_t)w * 16384);
    const uint4* gs = reinterpret_cast<const uint4*>((const char*)g_scores + (size_t)row * NCODES * 2);

    float mx = -1e30f;
#pragma unroll 4
    for (int it = 0; it < 32; it++) {
        uint4 v = gs[it * 32 + lane];
        srow[it * 32 + lane] = v;
        mx = fmaxf(mx, fmaxf(fmaxf(fmaxf(bf_lo(v.x), bf_hi(v.x)), fmaxf(bf_lo(v.y), bf_hi(v.y))),
                             fmaxf(fmaxf(bf_lo(v.z), bf_hi(v.z)), fmaxf(bf_lo(v.w), bf_hi(v.w)))));
    }
#pragma unroll
    for (int off = 16; off; off >>= 1)
        mx = fmaxf(mx, __shfl_xor_sync(0xFFFFFFFFu, mx, off));
    const float thr = mx - MARGIN;

#pragma unroll 4
    for (int it = 0; it < 32; it++) {
        uint4 v = srow[it * 32 + lane];
        int cb0 = it * 256 + lane * 8;
        float e[8] = { bf_lo(v.x), bf_hi(v.x), bf_lo(v.y), bf_hi(v.y),
                       bf_lo(v.z), bf_hi(v.z), bf_lo(v.w), bf_hi(v.w) };
#pragma unroll
        for (int j = 0; j < 8; j++) {
            if (e[j] >= thr) {
                int pos = atomicAdd(&s_cnt[w], 1);
                if (pos < 32) s_cand[w][pos] = (unsigned short)(cb0 + j);
            }
        }
    }
    __syncwarp();
    int nc = min(s_cnt[w], 32);

    // exact row norm a
    const float4* zr = reinterpret_cast<const float4*>(g_zt + (size_t)row * DIMD);
    float4 z0 = zr[lane * 2], z1 = zr[lane * 2 + 1];
    float a = 0.0f;
    a = fmaf(z0.x, z0.x, a); a = fmaf(z0.y, z0.y, a);
    a = fmaf(z0.z, z0.z, a); a = fmaf(z0.w, z0.w, a);
    a = fmaf(z1.x, z1.x, a); a = fmaf(z1.y, z1.y, a);
    a = fmaf(z1.z, z1.z, a); a = fmaf(z1.w, z1.w, a);
#pragma unroll
    for (int off = 16; off; off >>= 1)
        a += __shfl_xor_sync(0xFFFFFFFFu, a, off);

    unsigned long long best = ~0ULL;
    for (int i = 0; i < nc; i++) {
        int k = s_cand[w][i];
        const float4* er = reinterpret_cast<const float4*>(cb + (size_t)k * DIMD);
        float4 e0 = er[lane * 2], e1 = er[lane * 2 + 1];
        float dot = 0.0f;
        dot = fmaf(z0.x, e0.x, dot); dot = fmaf(z0.y, e0.y, dot);
        dot = fmaf(z0.z, e0.z, dot); dot = fmaf(z0.w, e0.w, dot);
        dot = fmaf(z1.x, e1.x, dot); dot = fmaf(z1.y, e1.y, dot);
        dot = fmaf(z1.z, e1.z, dot); dot = fmaf(z1.w, e1.w, dot);
#pragma unroll
        for (int off = 16; off; off >>= 1)
            dot += __shfl_xor_sync(0xFFFFFFFFu, dot, off);
        float dist = __fadd_rn(__fadd_rn(a, g_bsq[k]), -2.0f * dot);
        unsigned long long key = ((unsigned long long)__float_as_uint(dist) << 32) | (unsigned)k;
        if (key < best) best = key;
    }
    if (lane == 0) {
        int idx = (int)(best & 0xFFFFFFFFu);
        g_idx[row] = idx;
        if (out_size >= ZQ_ELEMS + NROWS) out[ZQ_ELEMS + row] = (float)idx;
    }
}

// ---------------- output + loss (unchanged, bit-clean in R2) ----------------
__global__ void k_output(const float* __restrict__ z, const float* __restrict__ cb,
                         float* __restrict__ out, int out_size) {
    int i = blockIdx.x * blockDim.x + threadIdx.x;
    float dsq = 0.0f;
    if (i < ZQ_ELEMS) {
        int p = i & 1023;
        int d = (i >> 10) & 255;
        int b = i >> 18;
        int n = (b << 10) | p;
        int idx = g_idx[n];
        float zv = z[i];
        float e  = cb[(size_t)idx * DIMD + d];
        float diff = __fadd_rn(e, -zv);
        if (i < out_size) out[i] = __fadd_rn(zv, diff);
        dsq = diff * diff;
    }
#pragma unroll
    for (int off = 16; off; off >>= 1)
        dsq += __shfl_xor_sync(0xFFFFFFFFu, dsq, off);
    __shared__ float warpsum[8];
    int lane = threadIdx.x & 31, w = threadIdx.x >> 5;
    if (lane == 0) warpsum[w] = dsq;
    __syncthreads();
    if (threadIdx.x == 0) {
        float s = 0.0f;
#pragma unroll
        for (int q = 0; q < 8; q++) s += warpsum[q];
        atomicAdd(&g_loss, s);
    }
}

__global__ void k_loss(float* __restrict__ out, int out_size) {
    if (out_size >= ZQ_ELEMS + NROWS + 1) {
        float mean = g_loss / (float)ZQ_ELEMS;
        out[ZQ_ELEMS + NROWS] = 0.25f * mean;
    }
}

extern "C" void kernel_launch(void* const* d_in, const int* in_sizes, int n_in,
                              void* d_out, int out_size) {
    const float* z;
    const float* cb;
    if (n_in >= 2 && in_sizes[0] == ZQ_ELEMS) {
        z = (const float*)d_in[0]; cb = (const float*)d_in[1];
    } else {
        z = (const float*)d_in[1]; cb = (const float*)d_in[0];
    }
    float* out = (float*)d_out;

    cudaFuncSetAttribute(k_gemm, cudaFuncAttributeMaxDynamicSharedMemorySize, 65536);
    cudaFuncSetAttribute(k_scan, cudaFuncAttributeMaxDynamicSharedMemorySize, 131072);

    k_prep_zt<<<(ZQ_ELEMS + 255) / 256, 256>>>(z);
    k_prep_zbf<<<(NROWS * 32 + 255) / 256, 256>>>();
    k_prep_cb<<<(NCODES * 32 + 255) / 256, 256>>>(cb);
    k_bsq<<<(NCODES + 255) / 256, 256>>>(cb);

    dim3 grid(NCODES / 128, NROWS / 128);  // (64, 128)
    k_gemm<<<grid, 256, 65536>>>();

    k_scan<<<NROWS / 8, 256, 131072>>>(cb, out, out_size);
    k_output<<<(ZQ_ELEMS + 255) / 256, 256>>>(z, cb, out, out_size);
    k_loss<<<1, 1>>>(out, out_size);
}

// round 5
// speedup vs baseline: 7.9119x; 1.8136x over previous
#include <cuda_runtime.h>
#include <cuda_bf16.h>
#include <cstdint>

#define NROWS    16384
#define NCODES   8192
#define DIMD     256
#define HWQ      1024
#define ZQ_ELEMS 4194304
#define MARGIN   2e-4f
#define CAP      512

// Scratch (device globals; no allocations allowed)
__device__ __align__(16) __nv_bfloat16 g_zbf[NROWS * DIMD];    // 8 MB
__device__ __align__(16) __nv_bfloat16 g_cbbf[NCODES * DIMD];  // 4 MB
__device__ __align__(16) float         g_zt[NROWS * DIMD];     // 16 MB exact fp32
__device__ float g_bsq[NCODES];
__device__ uint32_t g_rowmax[NROWS];          // ordered-uint encoded fp32 score max
__device__ int      g_cnt[NROWS];
__device__ __align__(16) uint2 g_cand[(size_t)NROWS * CAP];    // 64 MB (idx, score bits)
__device__ int   g_idx[NROWS];
__device__ float g_loss;

// ---------------- helpers ----------------
__device__ __forceinline__ uint32_t smem_u32(const void* p) {
    uint32_t a;
    asm("{ .reg .u64 t; cvta.to.shared.u64 t, %1; cvt.u32.u64 %0, t; }" : "=r"(a) : "l"(p));
    return a;
}
__device__ __forceinline__ uint32_t swz(uint32_t off) { return off ^ ((off >> 3) & 0x70); }
__device__ __forceinline__ uint32_t f2u(float f) {
    uint32_t b = __float_as_uint(f);
    return (b >> 31) ? ~b : (b | 0x80000000u);
}
__device__ __forceinline__ float u2f(uint32_t u) {
    return __uint_as_float((u >> 31) ? (u & 0x7FFFFFFFu) : ~u);
}

#define CP_ASYNC16(dst, src) \
    asm volatile("cp.async.cg.shared.global [%0], [%1], 16;" :: "r"(dst), "l"(src) : "memory")
#define CP_COMMIT() asm volatile("cp.async.commit_group;" ::: "memory")

#define LDSM_X4(r0, r1, r2, r3, addr) \
    asm volatile("ldmatrix.sync.aligned.m8n8.x4.shared.b16 {%0,%1,%2,%3}, [%4];" \
        : "=r"(r0), "=r"(r1), "=r"(r2), "=r"(r3) : "r"(addr))

#define MMA16816(d, a, b0, b1) \
    asm volatile("mma.sync.aligned.m16n8k16.row.col.f32.bf16.bf16.f32 " \
        "{%0,%1,%2,%3}, {%4,%5,%6,%7}, {%8,%9}, {%0,%1,%2,%3};" \
        : "+f"((d)[0]), "+f"((d)[1]), "+f"((d)[2]), "+f"((d)[3]) \
        : "r"((a)[0]), "r"((a)[1]), "r"((a)[2]), "r"((a)[3]), "r"(b0), "r"(b1))

// ---------------- init + prep ----------------
__global__ void k_init() {
    int i = blockIdx.x * blockDim.x + threadIdx.x;
    if (i < NROWS) { g_cnt[i] = 0; g_rowmax[i] = f2u(-1e30f); }
    if (i == 0) g_loss = 0.0f;
}

// tiled transpose: z (B,D,H,W) -> z_t [n][d]
__global__ void k_prep_zt(const float* __restrict__ z) {
    __shared__ float tile[32][33];
    int b = blockIdx.z;
    int d0 = blockIdx.y * 32, p0 = blockIdx.x * 32;
    const float* src = z + ((size_t)(b * DIMD + d0) << 10) + p0;
#pragma unroll
    for (int i = threadIdx.y; i < 32; i += 8)
        tile[i][threadIdx.x] = src[((size_t)i << 10) + threadIdx.x];
    __syncthreads();
    float* dst = g_zt + (size_t)(b * HWQ + p0) * DIMD + d0;
#pragma unroll
    for (int i = threadIdx.y; i < 32; i += 8)
        dst[(size_t)i * DIMD + threadIdx.x] = tile[threadIdx.x][i];
}

__global__ void k_prep_zbf() {
    int u = blockIdx.x * blockDim.x + threadIdx.x;
    if (u >= NROWS * 32) return;
    int n = u >> 5, d8 = (u & 31) * 8;
    const float4* src = reinterpret_cast<const float4*>(g_zt + (size_t)n * DIMD + d8);
    float4 f0 = src[0], f1 = src[1];
    __nv_bfloat162 h0 = __floats2bfloat162_rn(f0.x, f0.y);
    __nv_bfloat162 h1 = __floats2bfloat162_rn(f0.z, f0.w);
    __nv_bfloat162 h2 = __floats2bfloat162_rn(f1.x, f1.y);
    __nv_bfloat162 h3 = __floats2bfloat162_rn(f1.z, f1.w);
    uint4 q;
    q.x = *reinterpret_cast<uint32_t*>(&h0);
    q.y = *reinterpret_cast<uint32_t*>(&h1);
    q.z = *reinterpret_cast<uint32_t*>(&h2);
    q.w = *reinterpret_cast<uint32_t*>(&h3);
    *reinterpret_cast<uint4*>(g_zbf + (size_t)n * DIMD + d8) = q;
}

__global__ void k_prep_cb(const float* __restrict__ cb) {
    int u = blockIdx.x * blockDim.x + threadIdx.x;
    if (u >= NCODES * 32) return;
    int k = u >> 5, d8 = (u & 31) * 8;
    const float4* src = reinterpret_cast<const float4*>(cb + (size_t)k * DIMD + d8);
    float4 f0 = src[0], f1 = src[1];
    __nv_bfloat162 h0 = __floats2bfloat162_rn(f0.x, f0.y);
    __nv_bfloat162 h1 = __floats2bfloat162_rn(f0.z, f0.w);
    __nv_bfloat162 h2 = __floats2bfloat162_rn(f1.x, f1.y);
    __nv_bfloat162 h3 = __floats2bfloat162_rn(f1.z, f1.w);
    uint4 q;
    q.x = *reinterpret_cast<uint32_t*>(&h0);
    q.y = *reinterpret_cast<uint32_t*>(&h1);
    q.z = *reinterpret_cast<uint32_t*>(&h2);
    q.w = *reinterpret_cast<uint32_t*>(&h3);
    *reinterpret_cast<uint4*>(g_cbbf + (size_t)k * DIMD + d8) = q;
}

// warp per code
__global__ void k_bsq(const float* __restrict__ cb) {
    int w = (blockIdx.x * blockDim.x + threadIdx.x) >> 5;
    int lane = threadIdx.x & 31;
    if (w >= NCODES) return;
    const float4* row = reinterpret_cast<const float4*>(cb + (size_t)w * DIMD);
    float4 v0 = row[lane * 2], v1 = row[lane * 2 + 1];
    float s = 0.0f;
    s = fmaf(v0.x, v0.x, s); s = fmaf(v0.y, v0.y, s);
    s = fmaf(v0.z, v0.z, s); s = fmaf(v0.w, v0.w, s);
    s = fmaf(v1.x, v1.x, s); s = fmaf(v1.y, v1.y, s);
    s = fmaf(v1.z, v1.z, s); s = fmaf(v1.w, v1.w, s);
#pragma unroll
    for (int off = 16; off; off >>= 1)
        s += __shfl_xor_sync(0xFFFFFFFFu, s, off);
    if (lane == 0) g_bsq[w] = s;
}

// ---------------- bf16 HMMA GEMM + fused argmax/candidate epilogue ----------------
__global__ void __launch_bounds__(256, 2) k_gemm() {
    extern __shared__ __align__(1024) unsigned char smem[];
    const uint32_t sA = smem_u32(smem);        // 2 x 16KB
    const uint32_t sB = sA + 32768;            // 2 x 16KB
    __shared__ uint32_t s_rmax[128];

    const int t = threadIdx.x;
    const int lane = t & 31, wid = t >> 5;
    const int wy = wid >> 2, wx = wid & 3;
    const int m0 = blockIdx.y * 128, n0 = blockIdx.x * 128;

    const char* gA = (const char*)(g_zbf  + (size_t)m0 * DIMD);
    const char* gB = (const char*)(g_cbbf + (size_t)n0 * DIMD);

    const int ld_row[4] = { (t + 0) >> 3, (t + 256) >> 3, (t + 512) >> 3, (t + 768) >> 3 };
    const int ld_seg = t & 7;

    float acc[4][4][4];
#pragma unroll
    for (int a = 0; a < 4; a++)
#pragma unroll
        for (int b = 0; b < 4; b++)
#pragma unroll
            for (int c = 0; c < 4; c++) acc[a][b][c] = 0.0f;

#define ISSUE(c) do {                                                           \
    uint32_t dA = sA + ((c) & 1) * 16384;                                       \
    uint32_t dB = sB + ((c) & 1) * 16384;                                       \
    _Pragma("unroll")                                                           \
    for (int i = 0; i < 4; i++) {                                               \
        uint32_t off = swz((uint32_t)(ld_row[i] * 128 + ld_seg * 16));          \
        size_t go = (size_t)ld_row[i] * 512 + (c) * 128 + ld_seg * 16;          \
        CP_ASYNC16(dA + off, gA + go);                                          \
        CP_ASYNC16(dB + off, gB + go);                                          \
    }                                                                           \
    CP_COMMIT();                                                                \
} while (0)

    ISSUE(0);
    ISSUE(1);

    const int g = lane >> 3, r = lane & 7;
    const int aRow = wy * 64 + (g & 1) * 8 + r;
    const int bRow = wx * 32 + (g & 1) * 8 + r;
    const int kCol = (g >> 1) * 8;

#pragma unroll 1
    for (int c = 0; c < 4; c++) {
        if (c < 3) asm volatile("cp.async.wait_group 1;" ::: "memory");
        else       asm volatile("cp.async.wait_group 0;" ::: "memory");
        __syncthreads();

        const uint32_t bA = sA + (c & 1) * 16384;
        const uint32_t bB = sB + (c & 1) * 16384;
#pragma unroll
        for (int ks = 0; ks < 4; ks++) {
            uint32_t af[4][4], bfr[2][4];
#pragma unroll
            for (int mt = 0; mt < 4; mt++) {
                uint32_t off = (uint32_t)((aRow + mt * 16) * 128 + (kCol + ks * 16) * 2);
                LDSM_X4(af[mt][0], af[mt][1], af[mt][2], af[mt][3], bA + swz(off));
            }
#pragma unroll
            for (int bt = 0; bt < 2; bt++) {
                uint32_t off = (uint32_t)((bRow + bt * 16) * 128 + (kCol + ks * 16) * 2);
                LDSM_X4(bfr[bt][0], bfr[bt][1], bfr[bt][2], bfr[bt][3], bB + swz(off));
            }
#pragma unroll
            for (int mt = 0; mt < 4; mt++)
#pragma unroll
                for (int bt = 0; bt < 2; bt++) {
                    MMA16816(acc[mt][bt * 2 + 0], af[mt], bfr[bt][0], bfr[bt][2]);
                    MMA16816(acc[mt][bt * 2 + 1], af[mt], bfr[bt][1], bfr[bt][3]);
                }
        }
        __syncthreads();
        if (c < 2) ISSUE(c + 2);
    }
#undef ISSUE

    // ---- fused epilogue: score = 2*dot - bsq, per-row max + candidate push ----
    const int cRow = lane >> 2, cCol = (lane & 3) * 2;
    float bq[8];
#pragma unroll
    for (int nn = 0; nn < 4; nn++) {
        int col = n0 + wx * 32 + nn * 8 + cCol;
        bq[nn * 2 + 0] = g_bsq[col];
        bq[nn * 2 + 1] = g_bsq[col + 1];
    }

    if (t < 128) s_rmax[t] = 0u;
    __syncthreads();

    // phase A: per-row local max -> smem
#pragma unroll
    for (int mt = 0; mt < 4; mt++) {
#pragma unroll
        for (int h = 0; h < 2; h++) {
            float m = -1e30f;
#pragma unroll
            for (int nn = 0; nn < 4; nn++) {
                float s0 = fmaf(2.0f, acc[mt][nn][h * 2 + 0], -bq[nn * 2 + 0]);
                float s1 = fmaf(2.0f, acc[mt][nn][h * 2 + 1], -bq[nn * 2 + 1]);
                m = fmaxf(m, fmaxf(s0, s1));
            }
            atomicMax(&s_rmax[wy * 64 + mt * 16 + h * 8 + cRow], f2u(m));
        }
    }
    __syncthreads();
    if (t < 128) atomicMax(&g_rowmax[m0 + t], s_rmax[t]);

    // phase B: threshold = max(strip max, stale global max) - MARGIN; push
#pragma unroll
    for (int mt = 0; mt < 4; mt++) {
#pragma unroll
        for (int h = 0; h < 2; h++) {
            int rl = wy * 64 + mt * 16 + h * 8 + cRow;
            int row = m0 + rl;
            uint32_t gm = *(volatile uint32_t*)&g_rowmax[row];
            uint32_t tu = max(gm, s_rmax[rl]);
            float thr = u2f(tu) - MARGIN;
#pragma unroll
            for (int nn = 0; nn < 4; nn++) {
#pragma unroll
                for (int q = 0; q < 2; q++) {
                    float s = fmaf(2.0f, acc[mt][nn][h * 2 + q], -bq[nn * 2 + q]);
                    if (s >= thr) {
                        int pos = atomicAdd(&g_cnt[row], 1);
                        if (pos < CAP)
                            g_cand[(size_t)row * CAP + pos] =
                                make_uint2((unsigned)(n0 + wx * 32 + nn * 8 + cCol + q),
                                           __float_as_uint(s));
                    }
                }
            }
        }
    }
}

// ---------------- rescue: filter by final max, exact fp32 rescore ----------------
__global__ void __launch_bounds__(256) k_rescue(const float* __restrict__ cb,
                                                float* __restrict__ out, int out_size) {
    const int w = threadIdx.x >> 5, lane = threadIdx.x & 31;
    const int row = blockIdx.x * 8 + w;

    const float thr = u2f(g_rowmax[row]) - MARGIN;
    const int cnt = g_cnt[row];

    const float4* zr = reinterpret_cast<const float4*>(g_zt + (size_t)row * DIMD);
    float4 z0 = zr[lane * 2], z1 = zr[lane * 2 + 1];
    float a = 0.0f;
    a = fmaf(z0.x, z0.x, a); a = fmaf(z0.y, z0.y, a);
    a = fmaf(z0.z, z0.z, a); a = fmaf(z0.w, z0.w, a);
    a = fmaf(z1.x, z1.x, a); a = fmaf(z1.y, z1.y, a);
    a = fmaf(z1.z, z1.z, a); a = fmaf(z1.w, z1.w, a);
#pragma unroll
    for (int off = 16; off; off >>= 1)
        a += __shfl_xor_sync(0xFFFFFFFFu, a, off);

    unsigned long long best = ~0ULL;
    if (cnt <= CAP) {
        for (int i = 0; i < cnt; i++) {
            uint2 e = g_cand[(size_t)row * CAP + i];
            if (__uint_as_float(e.y) < thr) continue;
            int k = (int)e.x;
            const float4* er = reinterpret_cast<const float4*>(cb + (size_t)k * DIMD);
            float4 e0 = er[lane * 2], e1 = er[lane * 2 + 1];
            float dot = 0.0f;
            dot = fmaf(z0.x, e0.x, dot); dot = fmaf(z0.y, e0.y, dot);
            dot = fmaf(z0.z, e0.z, dot); dot = fmaf(z0.w, e0.w, dot);
            dot = fmaf(z1.x, e1.x, dot); dot = fmaf(z1.y, e1.y, dot);
            dot = fmaf(z1.z, e1.z, dot); dot = fmaf(z1.w, e1.w, dot);
#pragma unroll
            for (int off = 16; off; off >>= 1)
                dot += __shfl_xor_sync(0xFFFFFFFFu, dot, off);
            float dist = __fadd_rn(__fadd_rn(a, g_bsq[k]), -2.0f * dot);
            unsigned long long key = ((unsigned long long)__float_as_uint(dist) << 32) | (unsigned)k;
            if (key < best) best = key;
        }
    } else {
        // overflow fallback: exact scan of all codes (statistically ~never)
        for (int k = 0; k < NCODES; k++) {
            const float4* er = reinterpret_cast<const float4*>(cb + (size_t)k * DIMD);
            float4 e0 = er[lane * 2], e1 = er[lane * 2 + 1];
            float dot = 0.0f;
            dot = fmaf(z0.x, e0.x, dot); dot = fmaf(z0.y, e0.y, dot);
            dot = fmaf(z0.z, e0.z, dot); dot = fmaf(z0.w, e0.w, dot);
            dot = fmaf(z1.x, e1.x, dot); dot = fmaf(z1.y, e1.y, dot);
            dot = fmaf(z1.z, e1.z, dot); dot = fmaf(z1.w, e1.w, dot);
#pragma unroll
            for (int off = 16; off; off >>= 1)
                dot += __shfl_xor_sync(0xFFFFFFFFu, dot, off);
            float dist = __fadd_rn(__fadd_rn(a, g_bsq[k]), -2.0f * dot);
            unsigned long long key = ((unsigned long long)__float_as_uint(dist) << 32) | (unsigned)k;
            if (key < best) best = key;
        }
    }
    if (lane == 0) {
        int idx = (int)(best & 0xFFFFFFFFu);
        g_idx[row] = idx;
        if (out_size >= ZQ_ELEMS + NROWS) out[ZQ_ELEMS + row] = (float)idx;
    }
}

// ---------------- output + loss ----------------
__global__ void k_output(const float* __restrict__ z, const float* __restrict__ cb,
                         float* __restrict__ out, int out_size) {
    int i = blockIdx.x * blockDim.x + threadIdx.x;
    float dsq = 0.0f;
    if (i < ZQ_ELEMS) {
        int p = i & 1023;
        int d = (i >> 10) & 255;
        int b = i >> 18;
        int n = (b << 10) | p;
        int idx = g_idx[n];
        float zv = z[i];
        float e  = cb[(size_t)idx * DIMD + d];
        float diff = __fadd_rn(e, -zv);
        if (i < out_size) out[i] = __fadd_rn(zv, diff);
        dsq = diff * diff;
    }
#pragma unroll
    for (int off = 16; off; off >>= 1)
        dsq += __shfl_xor_sync(0xFFFFFFFFu, dsq, off);
    __shared__ float warpsum[8];
    int lane = threadIdx.x & 31, w = threadIdx.x >> 5;
    if (lane == 0) warpsum[w] = dsq;
    __syncthreads();
    if (threadIdx.x == 0) {
        float s = 0.0f;
#pragma unroll
        for (int q = 0; q < 8; q++) s += warpsum[q];
        atomicAdd(&g_loss, s);
    }
}

__global__ void k_loss(float* __restrict__ out, int out_size) {
    if (out_size >= ZQ_ELEMS + NROWS + 1) {
        float mean = g_loss / (float)ZQ_ELEMS;
        out[ZQ_ELEMS + NROWS] = 0.25f * mean;
    }
}

extern "C" void kernel_launch(void* const* d_in, const int* in_sizes, int n_in,
                              void* d_out, int out_size) {
    const float* z;
    const float* cb;
    if (n_in >= 2 && in_sizes[0] == ZQ_ELEMS) {
        z = (const float*)d_in[0]; cb = (const float*)d_in[1];
    } else {
        z = (const float*)d_in[1]; cb = (const float*)d_in[0];
    }
    float* out = (float*)d_out;

    cudaFuncSetAttribute(k_gemm, cudaFuncAttributeMaxDynamicSharedMemorySize, 65536);

    k_init<<<(NROWS + 255) / 256, 256>>>();
    {
        dim3 tg(32, 8, 16);
        k_prep_zt<<<tg, dim3(32, 8)>>>(z);
    }
    k_prep_zbf<<<(NROWS * 32 + 255) / 256, 256>>>();
    k_prep_cb<<<(NCODES * 32 + 255) / 256, 256>>>(cb);
    k_bsq<<<NCODES * 32 / 256, 256>>>(cb);

    dim3 grid(NCODES / 128, NROWS / 128);  // (64, 128)
    k_gemm<<<grid, 256, 65536>>>();

    k_rescue<<<NROWS / 8, 256>>>(cb, out, out_size);
    k_output<<<(ZQ_ELEMS + 255) / 256, 256>>>(z, cb, out, out_size);
    k_loss<<<1, 1>>>(out, out_size);
}